// round 10
// baseline (speedup 1.0000x reference)
#include <cuda_runtime.h>
#include <cuda_bf16.h>
#include <math_constants.h>
#include <cstdint>

// Problem constants
#define NU   8192
#define NL   8192     // per half
#define DD   512
#define CC   1000
#define INV_TAU 10.0f

// ---------------- device scratch ---------------------------------------------
__device__ __nv_bfloat16 g_aqh [NU * DD];
__device__ __nv_bfloat16 g_pqh [NU * DD];
__device__ __nv_bfloat16 g_suph[2 * NL * DD];     // class-sorted order
__device__ float g_rowsum[2 * NU];
__device__ int   g_labels[2 * NL];
__device__ int   g_counts[2 * CC];
__device__ int   g_offsets[2 * (CC + 1)];
__device__ int   g_cursor[2 * CC];
__device__ int   g_perm[2 * NL];

// ---------------- PTX helpers -------------------------------------------------
__device__ __forceinline__ uint32_t smem_u32(const void* p) {
    uint32_t a;
    asm("{ .reg .u64 t; cvta.to.shared.u64 t, %1; cvt.u32.u64 %0, t; }" : "=r"(a) : "l"(p));
    return a;
}
#define CP_ASYNC16(s, g) asm volatile("cp.async.cg.shared.global [%0], [%1], 16;" :: "r"(s), "l"(g))
#define CP_COMMIT()      asm volatile("cp.async.commit_group;" ::: "memory")
#define CP_WAIT(n)       asm volatile("cp.async.wait_group %0;" :: "n"(n) : "memory")

__device__ __forceinline__ void ldsm_x4(uint32_t* r, uint32_t addr) {
    asm volatile("ldmatrix.sync.aligned.m8n8.x4.shared.b16 {%0,%1,%2,%3}, [%4];"
        : "=r"(r[0]), "=r"(r[1]), "=r"(r[2]), "=r"(r[3]) : "r"(addr));
}
__device__ __forceinline__ void ldsm_x2(uint32_t* r, uint32_t addr) {
    asm volatile("ldmatrix.sync.aligned.m8n8.x2.shared.b16 {%0,%1}, [%2];"
        : "=r"(r[0]), "=r"(r[1]) : "r"(addr));
}
__device__ __forceinline__ void mma_bf16(float* c, const uint32_t* a, const uint32_t* b) {
    asm volatile("mma.sync.aligned.m16n8k16.row.col.f32.bf16.bf16.f32 "
        "{%0,%1,%2,%3},{%4,%5,%6,%7},{%8,%9},{%0,%1,%2,%3};"
        : "+f"(c[0]), "+f"(c[1]), "+f"(c[2]), "+f"(c[3])
        : "r"(a[0]), "r"(a[1]), "r"(a[2]), "r"(a[3]), "r"(b[0]), "r"(b[1]));
}

// ---------------- prep: labels (read-only) ------------------------------------
__global__ void labels_k(const float* __restrict__ oh) {
    int row  = blockIdx.x * (blockDim.x >> 5) + (threadIdx.x >> 5);
    int lane = threadIdx.x & 31;
    if (row >= 2 * NL) return;
    const float* r = oh + (size_t)row * CC;
    int lab = -1;
    for (int c = lane; c < CC; c += 32)
        if (r[c] > 0.5f) lab = c;
    #pragma unroll
    for (int o = 16; o; o >>= 1) lab = max(lab, __shfl_xor_sync(0xffffffffu, lab, o));
    if (lane == 0) g_labels[row] = lab;
}
__global__ void zero_counts_k() {
    int i = blockIdx.x * blockDim.x + threadIdx.x;
    if (i < 2 * CC) g_counts[i] = 0;
}
__global__ void count_k() {
    int i = blockIdx.x * blockDim.x + threadIdx.x;
    if (i >= 2 * NL) return;
    int half = i / NL;
    atomicAdd(&g_counts[half * CC + g_labels[i]], 1);
}
__global__ void offsets_k() {
    int h = threadIdx.x;
    if (h >= 2) return;
    int off = 0;
    for (int c = 0; c < CC; c++) {
        g_offsets[h * (CC + 1) + c] = off;
        g_cursor[h * CC + c] = off;
        off += g_counts[h * CC + c];
    }
    g_offsets[h * (CC + 1) + CC] = off;
}
__global__ void scatter_k() {
    int i = blockIdx.x * blockDim.x + threadIdx.x;
    if (i >= 2 * NL) return;
    int half = i / NL;
    int s    = i - half * NL;
    int pos  = atomicAdd(&g_cursor[half * CC + g_labels[i]], 1);
    g_perm[half * NL + pos] = s;
}

// ---------------- l2 normalize -> bf16 (no copy) ------------------------------
__global__ void norm_q_k(const float* __restrict__ src, int sel) {
    int row  = blockIdx.x * (blockDim.x >> 5) + (threadIdx.x >> 5);
    int lane = threadIdx.x & 31;
    if (row >= NU) return;
    __nv_bfloat16* nb = ((sel == 0) ? g_aqh : g_pqh) + (size_t)row * DD;
    const float4* s4 = (const float4*)(src + (size_t)row * DD);
    float4 v[4];
    float acc = 0.f;
    #pragma unroll
    for (int i = 0; i < 4; i++) {
        v[i] = s4[lane + 32 * i];
        acc += v[i].x * v[i].x + v[i].y * v[i].y + v[i].z * v[i].z + v[i].w * v[i].w;
    }
    #pragma unroll
    for (int o = 16; o; o >>= 1) acc += __shfl_xor_sync(0xffffffffu, acc, o);
    float inv = 1.0f / fmaxf(sqrtf(acc), 1e-12f);
    #pragma unroll
    for (int i = 0; i < 4; i++) {
        int c = (lane + 32 * i) * 4;
        nb[c + 0] = __float2bfloat16(v[i].x * inv);
        nb[c + 1] = __float2bfloat16(v[i].y * inv);
        nb[c + 2] = __float2bfloat16(v[i].z * inv);
        nb[c + 3] = __float2bfloat16(v[i].w * inv);
    }
}
__global__ void norm_sup_k(const float* __restrict__ lb) {
    int row  = blockIdx.x * (blockDim.x >> 5) + (threadIdx.x >> 5);
    int lane = threadIdx.x & 31;
    if (row >= 2 * NL) return;
    int half = row / NL;
    int pos  = row - half * NL;
    int srow = half * NL + g_perm[half * NL + pos];
    const float* s = lb + (size_t)srow * DD;
    float v[16];
    float acc = 0.f;
    #pragma unroll
    for (int i = 0; i < 16; i++) { v[i] = s[lane + 32 * i]; acc += v[i] * v[i]; }
    #pragma unroll
    for (int o = 16; o; o >>= 1) acc += __shfl_xor_sync(0xffffffffu, acc, o);
    float inv = 1.0f / fmaxf(sqrtf(acc), 1e-12f);
    __nv_bfloat16* d = g_suph + (size_t)row * DD;
    #pragma unroll
    for (int i = 0; i < 16; i++) d[lane + 32 * i] = __float2bfloat16(v[i] * inv);
}

// zero the accumulation targets (output ulb region + rowsums)
__global__ void zero_acc_k(float* __restrict__ ulb) {
    size_t i = (size_t)blockIdx.x * blockDim.x + threadIdx.x;
    size_t n = (size_t)2 * NU * CC;
    if (i < n) ulb[i] = 0.f;
    if (i < 2 * NU) g_rowsum[i] = 0.f;
}

// ---------------- heterogeneous kernel: GEMM+epilogue  OR  copy ---------------
#define BM 128
#define BN 128
#define BKK 32
#define STAGES 4
#define NKIT (DD / BKK)                 // 16
#define SROW 80
#define TILE_BYTES (BM * SROW)          // 10240
#define STAGE_BYTES (2 * TILE_BYTES)    // 20480
#define EP_PITCH 129
#define C2C_OFF (STAGES * STAGE_BYTES)  // 81920
#define GEMM_SMEM (C2C_OFF + 512)       // 82432

#define NGEMM 8192
#define NCOPY 4096
#define NTOT  (NGEMM + NCOPY)           // 12288; bx%3==2 -> copy (exactly 4096)

// copy segment bounds in float4 units (output layout = concatenation)
#define S0 1048576u                 // anchor end
#define S1 2097152u                 // pos end
#define S2 4194304u                 // lb end
#define S3 8290304u                 // oh end
#define S4 12386304u                // lgx end (total)
#define COPY_CHUNK 3024u            // S4 / NCOPY exactly

__global__ void __launch_bounds__(256) gemm_copy_k(
    const float4* __restrict__ anchor, const float4* __restrict__ pos,
    const float4* __restrict__ lb, const float4* __restrict__ oh,
    const float4* __restrict__ lgx,
    float4* __restrict__ out4, float* __restrict__ ulbbase)
{
    extern __shared__ __align__(16) char smem[];
    const int tid = threadIdx.x;
    const uint32_t bx = blockIdx.x;
    const uint32_t bn = bx / 3u;
    const uint32_t br = bx - bn * 3u;

    if (br == 2u) {
        // ---------------- copy block (bn in 0..4095) ----------------
        uint32_t start = bn * COPY_CHUNK;
        uint32_t end   = start + COPY_CHUNK;
        if (end > S4) end = S4;
        for (uint32_t i = start + tid; i < end; i += 256) {
            float4 v;
            if      (i < S0) v = anchor[i];
            else if (i < S1) v = pos[i - S0];
            else if (i < S2) v = lb[i - S1];
            else if (i < S3) v = oh[i - S2];
            else             v = lgx[i - S3];
            out4[i] = v;
        }
        return;
    }

    // ---------------- GEMM block: g in 0..8191 ----------------
    const uint32_t g = 2u * bn + br;
    const int gx = g & 63;                   // n tile
    const int gy = (g >> 6) & 63;            // m tile
    const int z  = g >> 12;                  // half

    const uint32_t sbase = smem_u32(smem);
    const int wid  = tid >> 5;
    const int lane = tid & 31;
    const int wr   = wid & 1;
    const int wc   = wid >> 1;

    const __nv_bfloat16* A = (z == 0) ? g_aqh : g_pqh;
    const __nv_bfloat16* B = g_suph + (size_t)z * NL * DD;
    const int m0 = gy * BM;
    const int n0 = gx * BN;
    const __nv_bfloat16* Abase = A + (size_t)m0 * DD;
    const __nv_bfloat16* Bbase = B + (size_t)n0 * DD;

    const int r0 = tid >> 2, r1 = r0 + 64;
    const int c0 = (tid & 3) * 8;

    float acc[4][4][4];
    #pragma unroll
    for (int mi = 0; mi < 4; mi++)
        #pragma unroll
        for (int ni = 0; ni < 4; ni++)
            #pragma unroll
            for (int q = 0; q < 4; q++) acc[mi][ni][q] = 0.f;

    #pragma unroll
    for (int s = 0; s < STAGES - 1; s++) {
        uint32_t sA = sbase + s * STAGE_BYTES;
        uint32_t sB = sA + TILE_BYTES;
        const __nv_bfloat16* Ak = Abase + s * BKK;
        const __nv_bfloat16* Bk = Bbase + s * BKK;
        CP_ASYNC16(sA + r0 * SROW + c0 * 2, Ak + (size_t)r0 * DD + c0);
        CP_ASYNC16(sA + r1 * SROW + c0 * 2, Ak + (size_t)r1 * DD + c0);
        CP_ASYNC16(sB + r0 * SROW + c0 * 2, Bk + (size_t)r0 * DD + c0);
        CP_ASYNC16(sB + r1 * SROW + c0 * 2, Bk + (size_t)r1 * DD + c0);
        CP_COMMIT();
    }

    const uint32_t aOff = (uint32_t)(wr * 64 + (lane & 15)) * SROW + (lane >> 4) * 16;
    const uint32_t bOff = (uint32_t)(wc * 32 + (lane & 7)) * SROW + ((lane >> 3) & 1) * 16;

    for (int kc = 0; kc < NKIT; kc++) {
        const int st = kc % STAGES;
        CP_WAIT(STAGES - 2);
        __syncthreads();

        const int pf = kc + STAGES - 1;
        if (pf < NKIT) {
            const int ps = pf % STAGES;
            uint32_t sA = sbase + ps * STAGE_BYTES;
            uint32_t sB = sA + TILE_BYTES;
            const __nv_bfloat16* Ak = Abase + pf * BKK;
            const __nv_bfloat16* Bk = Bbase + pf * BKK;
            CP_ASYNC16(sA + r0 * SROW + c0 * 2, Ak + (size_t)r0 * DD + c0);
            CP_ASYNC16(sA + r1 * SROW + c0 * 2, Ak + (size_t)r1 * DD + c0);
            CP_ASYNC16(sB + r0 * SROW + c0 * 2, Bk + (size_t)r0 * DD + c0);
            CP_ASYNC16(sB + r1 * SROW + c0 * 2, Bk + (size_t)r1 * DD + c0);
        }
        CP_COMMIT();

        const uint32_t sA = sbase + st * STAGE_BYTES;
        const uint32_t sB = sA + TILE_BYTES;
        #pragma unroll
        for (int kk = 0; kk < 2; kk++) {
            uint32_t aF[4][4], bF[4][2];
            #pragma unroll
            for (int mi = 0; mi < 4; mi++)
                ldsm_x4(aF[mi], sA + aOff + (uint32_t)mi * 16 * SROW + kk * 32);
            #pragma unroll
            for (int ni = 0; ni < 4; ni++)
                ldsm_x2(bF[ni], sB + bOff + (uint32_t)ni * 8 * SROW + kk * 32);
            #pragma unroll
            for (int mi = 0; mi < 4; mi++)
                #pragma unroll
                for (int ni = 0; ni < 4; ni++)
                    mma_bf16(acc[mi][ni], aF[mi], bF[ni]);
        }
    }

    // ---- epilogue: exp -> smem, per-row contiguous segment sums, atomics ----
    CP_WAIT(0);
    __syncthreads();

    float* ep    = (float*)smem;
    int*   c2c_s = (int*)(smem + C2C_OFF);

    const int ebr = wr * 64 + (lane >> 2);
    const int ebc = wc * 32 + (lane & 3) * 2;
    #pragma unroll
    for (int mi = 0; mi < 4; mi++) {
        #pragma unroll
        for (int ni = 0; ni < 4; ni++) {
            int rr = ebr + mi * 16, cc2 = ebc + ni * 8;
            ep[rr * EP_PITCH + cc2]           = __expf(acc[mi][ni][0] * INV_TAU);
            ep[rr * EP_PITCH + cc2 + 1]       = __expf(acc[mi][ni][1] * INV_TAU);
            ep[(rr + 8) * EP_PITCH + cc2]     = __expf(acc[mi][ni][2] * INV_TAU);
            ep[(rr + 8) * EP_PITCH + cc2 + 1] = __expf(acc[mi][ni][3] * INV_TAU);
        }
    }
    if (tid < BN) {
        const int* offs = g_offsets + z * (CC + 1);
        int v = n0 + tid;
        int lo = 0, hi = CC - 1;
        while (lo < hi) { int mid = (lo + hi + 1) >> 1; if (offs[mid] <= v) lo = mid; else hi = mid - 1; }
        c2c_s[tid] = lo;
    }
    __syncthreads();

    if (tid < BM) {
        float* orow = ulbbase + (size_t)z * NU * CC + (size_t)(m0 + tid) * CC;
        const float* er = ep + tid * EP_PITCH;
        float run = 0.f, rs = 0.f;
        int cls = c2c_s[0];
        #pragma unroll 4
        for (int j = 0; j < BN; j++) {
            int c2 = c2c_s[j];
            float e = er[j];
            if (c2 != cls) { atomicAdd(&orow[cls], run); run = 0.f; cls = c2; }
            run += e;
            rs  += e;
        }
        atomicAdd(&orow[cls], run);
        atomicAdd(&g_rowsum[z * NU + m0 + tid], rs);
    }
}

// ---------------- normalize + zero empty classes ------------------------------
__global__ void __launch_bounds__(256) normalize_k(float* __restrict__ ulbbase) {
    int u = blockIdx.x;
    int z = blockIdx.y;
    float inv = 1.0f / g_rowsum[z * NU + u];
    const int* offs = g_offsets + z * (CC + 1);
    float* orow = ulbbase + (size_t)z * NU * CC + (size_t)u * CC;
    for (int c = threadIdx.x; c < CC; c += 256) {
        float v = orow[c];
        orow[c] = (offs[c + 1] > offs[c]) ? v * inv : 0.f;
    }
}

// ---------------- launch ------------------------------------------------------
extern "C" void kernel_launch(void* const* d_in, const int* in_sizes, int n_in,
                              void* d_out, int out_size) {
    const float* anchor = (const float*)d_in[0];
    const float* pos    = (const float*)d_in[1];
    const float* lb     = (const float*)d_in[2];
    const float* oh     = (const float*)d_in[3];
    const float* lgx    = (const float*)d_in[4];
    float* out = (float*)d_out;

    const size_t nA  = (size_t)NU * DD;
    const size_t nP  = (size_t)NU * DD;
    const size_t nL  = (size_t)2 * NL * DD;
    const size_t nOH = (size_t)2 * NL * CC;
    const size_t nLG = (size_t)2 * NL * CC;
    size_t oU1 = nA + nP + nL + nOH + nLG;

    // prep: labels + counting sort + normalizes (read-only on inputs)
    labels_k<<<(2 * NL) / 8, 256>>>(oh);
    zero_counts_k<<<(2 * CC + 255) / 256, 256>>>();
    count_k<<<(2 * NL + 255) / 256, 256>>>();
    offsets_k<<<1, 2>>>();
    scatter_k<<<(2 * NL + 255) / 256, 256>>>();

    norm_q_k<<<NU / 8, 256>>>(anchor, 0);
    norm_q_k<<<NU / 8, 256>>>(pos,    1);
    norm_sup_k<<<(2 * NL) / 8, 256>>>(lb);

    zero_acc_k<<<(int)(((size_t)2 * NU * CC + 255) / 256), 256>>>(out + oU1);

    // heterogeneous launch: 8192 GEMM blocks + 4096 copy blocks interleaved
    cudaFuncSetAttribute(gemm_copy_k, cudaFuncAttributeMaxDynamicSharedMemorySize, GEMM_SMEM);
    gemm_copy_k<<<NTOT, 256, GEMM_SMEM>>>(
        (const float4*)anchor, (const float4*)pos, (const float4*)lb,
        (const float4*)oh, (const float4*)lgx,
        (float4*)out, out + oU1);

    // normalize + zero empty classes
    dim3 gn(NU, 2);
    normalize_k<<<gn, 256>>>(out + oU1);
}

// round 11
// speedup vs baseline: 1.1869x; 1.1869x over previous
#include <cuda_runtime.h>
#include <cuda_bf16.h>
#include <math_constants.h>
#include <cstdint>

// Problem constants
#define NU   8192
#define NL   8192     // per half
#define DD   512
#define CC   1000
#define INV_TAU 10.0f

// ---------------- device scratch ---------------------------------------------
__device__ __nv_bfloat16 g_aqh [NU * DD];
__device__ __nv_bfloat16 g_pqh [NU * DD];
__device__ __nv_bfloat16 g_suph[2 * NL * DD];     // class-sorted order
__device__ float g_rowsum[2 * NU];
__device__ int   g_labels[2 * NL];
__device__ int   g_counts[2 * CC];
__device__ int   g_offsets[2 * (CC + 1)];
__device__ int   g_cursor[2 * CC];
__device__ int   g_perm[2 * NL];

// ---------------- PTX helpers -------------------------------------------------
__device__ __forceinline__ uint32_t smem_u32(const void* p) {
    uint32_t a;
    asm("{ .reg .u64 t; cvta.to.shared.u64 t, %1; cvt.u32.u64 %0, t; }" : "=r"(a) : "l"(p));
    return a;
}
#define CP_ASYNC16(s, g) asm volatile("cp.async.cg.shared.global [%0], [%1], 16;" :: "r"(s), "l"(g))
#define CP_COMMIT()      asm volatile("cp.async.commit_group;" ::: "memory")
#define CP_WAIT(n)       asm volatile("cp.async.wait_group %0;" :: "n"(n) : "memory")

__device__ __forceinline__ void ldsm_x4(uint32_t* r, uint32_t addr) {
    asm volatile("ldmatrix.sync.aligned.m8n8.x4.shared.b16 {%0,%1,%2,%3}, [%4];"
        : "=r"(r[0]), "=r"(r[1]), "=r"(r[2]), "=r"(r[3]) : "r"(addr));
}
__device__ __forceinline__ void ldsm_x2(uint32_t* r, uint32_t addr) {
    asm volatile("ldmatrix.sync.aligned.m8n8.x2.shared.b16 {%0,%1}, [%2];"
        : "=r"(r[0]), "=r"(r[1]) : "r"(addr));
}
__device__ __forceinline__ void mma_bf16(float* c, const uint32_t* a, const uint32_t* b) {
    asm volatile("mma.sync.aligned.m16n8k16.row.col.f32.bf16.bf16.f32 "
        "{%0,%1,%2,%3},{%4,%5,%6,%7},{%8,%9},{%0,%1,%2,%3};"
        : "+f"(c[0]), "+f"(c[1]), "+f"(c[2]), "+f"(c[3])
        : "r"(a[0]), "r"(a[1]), "r"(a[2]), "r"(a[3]), "r"(b[0]), "r"(b[1]));
}

// ---------------- copies ------------------------------------------------------
__global__ void copy_f4(const float4* __restrict__ src, float4* __restrict__ dst, int n4) {
    int i = blockIdx.x * blockDim.x + threadIdx.x;
    if (i < n4) dst[i] = src[i];
}

// fused copy + l2-normalize -> bf16 (anchors / positives), warp per row
__global__ void copy_norm_q_k(const float* __restrict__ src, float* __restrict__ dstcopy, int sel) {
    int row  = blockIdx.x * (blockDim.x >> 5) + (threadIdx.x >> 5);
    int lane = threadIdx.x & 31;
    if (row >= NU) return;
    __nv_bfloat16* nb = ((sel == 0) ? g_aqh : g_pqh) + (size_t)row * DD;
    const float4* s4 = (const float4*)(src + (size_t)row * DD);
    float4* d4 = (float4*)(dstcopy + (size_t)row * DD);
    float4 v[4];
    float acc = 0.f;
    #pragma unroll
    for (int i = 0; i < 4; i++) {
        v[i] = s4[lane + 32 * i];
        acc += v[i].x * v[i].x + v[i].y * v[i].y + v[i].z * v[i].z + v[i].w * v[i].w;
    }
    #pragma unroll
    for (int o = 16; o; o >>= 1) acc += __shfl_xor_sync(0xffffffffu, acc, o);
    float inv = 1.0f / fmaxf(sqrtf(acc), 1e-12f);
    #pragma unroll
    for (int i = 0; i < 4; i++) {
        d4[lane + 32 * i] = v[i];
        int c = (lane + 32 * i) * 4;
        nb[c + 0] = __float2bfloat16(v[i].x * inv);
        nb[c + 1] = __float2bfloat16(v[i].y * inv);
        nb[c + 2] = __float2bfloat16(v[i].z * inv);
        nb[c + 3] = __float2bfloat16(v[i].w * inv);
    }
}

// fused copy + label extraction for one_hot, warp per row
__global__ void copy_labels_k(const float* __restrict__ oh, float* __restrict__ dstcopy) {
    int row  = blockIdx.x * (blockDim.x >> 5) + (threadIdx.x >> 5);
    int lane = threadIdx.x & 31;
    if (row >= 2 * NL) return;
    const float* r = oh + (size_t)row * CC;
    float* d = dstcopy + (size_t)row * CC;
    int lab = -1;
    for (int c = lane; c < CC; c += 32) {
        float v = r[c];
        d[c] = v;
        if (v > 0.5f) lab = c;
    }
    #pragma unroll
    for (int o = 16; o; o >>= 1) lab = max(lab, __shfl_xor_sync(0xffffffffu, lab, o));
    if (lane == 0) g_labels[row] = lab;
}

// ---------------- counting sort ----------------------------------------------
__global__ void zero_counts_k() {
    int i = blockIdx.x * blockDim.x + threadIdx.x;
    if (i < 2 * CC) g_counts[i] = 0;
}
__global__ void count_k() {
    int i = blockIdx.x * blockDim.x + threadIdx.x;
    if (i >= 2 * NL) return;
    int half = i / NL;
    atomicAdd(&g_counts[half * CC + g_labels[i]], 1);
}
// parallel exclusive scan over counts -> offsets & cursor (one block per half)
__global__ void offsets_scan_k() {
    __shared__ int ws[32];
    int h    = blockIdx.x;
    int tid  = threadIdx.x;
    int lane = tid & 31, wid = tid >> 5;
    int v = (tid < CC) ? g_counts[h * CC + tid] : 0;
    int x = v;
    #pragma unroll
    for (int o = 1; o < 32; o <<= 1) {
        int y = __shfl_up_sync(0xffffffffu, x, o);
        if (lane >= o) x += y;
    }
    if (lane == 31) ws[wid] = x;
    __syncthreads();
    if (wid == 0) {
        int s = ws[lane];
        #pragma unroll
        for (int o = 1; o < 32; o <<= 1) {
            int y = __shfl_up_sync(0xffffffffu, s, o);
            if (lane >= o) s += y;
        }
        ws[lane] = s;
    }
    __syncthreads();
    int incl = x + (wid > 0 ? ws[wid - 1] : 0);
    int excl = incl - v;
    if (tid < CC) {
        g_offsets[h * (CC + 1) + tid] = excl;
        g_cursor[h * CC + tid] = excl;
    }
    if (tid == CC) g_offsets[h * (CC + 1) + CC] = excl;   // v=0 here -> total
}
__global__ void scatter_k() {
    int i = blockIdx.x * blockDim.x + threadIdx.x;
    if (i >= 2 * NL) return;
    int half = i / NL;
    int s    = i - half * NL;
    int pos  = atomicAdd(&g_cursor[half * CC + g_labels[i]], 1);
    g_perm[half * NL + pos] = s;
}

// supports: normalize, write in class-sorted (perm) order
__global__ void norm_sup_k(const float* __restrict__ lb) {
    int row  = blockIdx.x * (blockDim.x >> 5) + (threadIdx.x >> 5);
    int lane = threadIdx.x & 31;
    if (row >= 2 * NL) return;
    int half = row / NL;
    int pos  = row - half * NL;
    int srow = half * NL + g_perm[half * NL + pos];
    const float* s = lb + (size_t)srow * DD;
    float v[16];
    float acc = 0.f;
    #pragma unroll
    for (int i = 0; i < 16; i++) { v[i] = s[lane + 32 * i]; acc += v[i] * v[i]; }
    #pragma unroll
    for (int o = 16; o; o >>= 1) acc += __shfl_xor_sync(0xffffffffu, acc, o);
    float inv = 1.0f / fmaxf(sqrtf(acc), 1e-12f);
    __nv_bfloat16* d = g_suph + (size_t)row * DD;
    #pragma unroll
    for (int i = 0; i < 16; i++) d[lane + 32 * i] = __float2bfloat16(v[i] * inv);
}

// zero the accumulation targets (output ulb region + rowsums)
__global__ void zero_acc_k(float* __restrict__ ulb) {
    size_t i = (size_t)blockIdx.x * blockDim.x + threadIdx.x;
    size_t n = (size_t)2 * NU * CC;
    if (i < n) ulb[i] = 0.f;
    if (i < 2 * NU) g_rowsum[i] = 0.f;
}

// ---------------- GEMM + exp + class partial-sum epilogue --------------------
#define BM 128
#define BN 128
#define BKK 32
#define STAGES 4
#define NKIT (DD / BKK)                 // 16
#define SROW 80
#define TILE_BYTES (BM * SROW)          // 10240
#define STAGE_BYTES (2 * TILE_BYTES)    // 20480
#define EP_PITCH 129
#define C2C_OFF (STAGES * STAGE_BYTES)  // 81920
#define GEMM_SMEM (C2C_OFF + 512)       // 82432

__global__ void __launch_bounds__(256) gemm_fused_k(float* __restrict__ ulbbase) {
    extern __shared__ __align__(16) char smem[];
    const uint32_t sbase = smem_u32(smem);

    const int tid  = threadIdx.x;
    const int wid  = tid >> 5;
    const int lane = tid & 31;
    const int wr   = wid & 1;
    const int wc   = wid >> 1;

    const int z  = blockIdx.z;
    const __nv_bfloat16* A = (z == 0) ? g_aqh : g_pqh;
    const __nv_bfloat16* B = g_suph + (size_t)z * NL * DD;
    const int m0 = blockIdx.y * BM;
    const int n0 = blockIdx.x * BN;
    const __nv_bfloat16* Abase = A + (size_t)m0 * DD;
    const __nv_bfloat16* Bbase = B + (size_t)n0 * DD;

    const int r0 = tid >> 2, r1 = r0 + 64;
    const int c0 = (tid & 3) * 8;

    float acc[4][4][4];
    #pragma unroll
    for (int mi = 0; mi < 4; mi++)
        #pragma unroll
        for (int ni = 0; ni < 4; ni++)
            #pragma unroll
            for (int q = 0; q < 4; q++) acc[mi][ni][q] = 0.f;

    #pragma unroll
    for (int s = 0; s < STAGES - 1; s++) {
        uint32_t sA = sbase + s * STAGE_BYTES;
        uint32_t sB = sA + TILE_BYTES;
        const __nv_bfloat16* Ak = Abase + s * BKK;
        const __nv_bfloat16* Bk = Bbase + s * BKK;
        CP_ASYNC16(sA + r0 * SROW + c0 * 2, Ak + (size_t)r0 * DD + c0);
        CP_ASYNC16(sA + r1 * SROW + c0 * 2, Ak + (size_t)r1 * DD + c0);
        CP_ASYNC16(sB + r0 * SROW + c0 * 2, Bk + (size_t)r0 * DD + c0);
        CP_ASYNC16(sB + r1 * SROW + c0 * 2, Bk + (size_t)r1 * DD + c0);
        CP_COMMIT();
    }

    const uint32_t aOff = (uint32_t)(wr * 64 + (lane & 15)) * SROW + (lane >> 4) * 16;
    const uint32_t bOff = (uint32_t)(wc * 32 + (lane & 7)) * SROW + ((lane >> 3) & 1) * 16;

    for (int kc = 0; kc < NKIT; kc++) {
        const int st = kc % STAGES;
        CP_WAIT(STAGES - 2);
        __syncthreads();

        const int pf = kc + STAGES - 1;
        if (pf < NKIT) {
            const int ps = pf % STAGES;
            uint32_t sA = sbase + ps * STAGE_BYTES;
            uint32_t sB = sA + TILE_BYTES;
            const __nv_bfloat16* Ak = Abase + pf * BKK;
            const __nv_bfloat16* Bk = Bbase + pf * BKK;
            CP_ASYNC16(sA + r0 * SROW + c0 * 2, Ak + (size_t)r0 * DD + c0);
            CP_ASYNC16(sA + r1 * SROW + c0 * 2, Ak + (size_t)r1 * DD + c0);
            CP_ASYNC16(sB + r0 * SROW + c0 * 2, Bk + (size_t)r0 * DD + c0);
            CP_ASYNC16(sB + r1 * SROW + c0 * 2, Bk + (size_t)r1 * DD + c0);
        }
        CP_COMMIT();

        const uint32_t sA = sbase + st * STAGE_BYTES;
        const uint32_t sB = sA + TILE_BYTES;
        #pragma unroll
        for (int kk = 0; kk < 2; kk++) {
            uint32_t aF[4][4], bF[4][2];
            #pragma unroll
            for (int mi = 0; mi < 4; mi++)
                ldsm_x4(aF[mi], sA + aOff + (uint32_t)mi * 16 * SROW + kk * 32);
            #pragma unroll
            for (int ni = 0; ni < 4; ni++)
                ldsm_x2(bF[ni], sB + bOff + (uint32_t)ni * 8 * SROW + kk * 32);
            #pragma unroll
            for (int mi = 0; mi < 4; mi++)
                #pragma unroll
                for (int ni = 0; ni < 4; ni++)
                    mma_bf16(acc[mi][ni], aF[mi], bF[ni]);
        }
    }

    // ---- epilogue: exp -> smem, per-row contiguous segment sums, atomics ----
    CP_WAIT(0);
    __syncthreads();     // stages fully consumed; safe to overwrite with ep tile

    float* ep    = (float*)smem;              // 128 x EP_PITCH
    int*   c2c_s = (int*)(smem + C2C_OFF);

    const int ebr = wr * 64 + (lane >> 2);
    const int ebc = wc * 32 + (lane & 3) * 2;
    #pragma unroll
    for (int mi = 0; mi < 4; mi++) {
        #pragma unroll
        for (int ni = 0; ni < 4; ni++) {
            int rr = ebr + mi * 16, cc2 = ebc + ni * 8;
            ep[rr * EP_PITCH + cc2]           = __expf(acc[mi][ni][0] * INV_TAU);
            ep[rr * EP_PITCH + cc2 + 1]       = __expf(acc[mi][ni][1] * INV_TAU);
            ep[(rr + 8) * EP_PITCH + cc2]     = __expf(acc[mi][ni][2] * INV_TAU);
            ep[(rr + 8) * EP_PITCH + cc2 + 1] = __expf(acc[mi][ni][3] * INV_TAU);
        }
    }
    if (tid < BN) {
        const int* offs = g_offsets + z * (CC + 1);
        int v = n0 + tid;
        int lo = 0, hi = CC - 1;
        while (lo < hi) { int mid = (lo + hi + 1) >> 1; if (offs[mid] <= v) lo = mid; else hi = mid - 1; }
        c2c_s[tid] = lo;
    }
    __syncthreads();

    if (tid < BM) {
        float* orow = ulbbase + (size_t)z * NU * CC + (size_t)(m0 + tid) * CC;
        const float* er = ep + tid * EP_PITCH;
        float run = 0.f, rs = 0.f;
        int cls = c2c_s[0];
        #pragma unroll 4
        for (int j = 0; j < BN; j++) {
            int c2 = c2c_s[j];
            float e = er[j];
            if (c2 != cls) { atomicAdd(&orow[cls], run); run = 0.f; cls = c2; }
            run += e;
            rs  += e;
        }
        atomicAdd(&orow[cls], run);
        atomicAdd(&g_rowsum[z * NU + m0 + tid], rs);
    }
}

// ---------------- normalize + zero empty classes ------------------------------
__global__ void __launch_bounds__(256) normalize_k(float* __restrict__ ulbbase) {
    int u = blockIdx.x;
    int z = blockIdx.y;
    float inv = 1.0f / g_rowsum[z * NU + u];
    const int* offs = g_offsets + z * (CC + 1);
    float* orow = ulbbase + (size_t)z * NU * CC + (size_t)u * CC;
    for (int c = threadIdx.x; c < CC; c += 256) {
        float v = orow[c];
        orow[c] = (offs[c + 1] > offs[c]) ? v * inv : 0.f;
    }
}

// ---------------- launch ------------------------------------------------------
extern "C" void kernel_launch(void* const* d_in, const int* in_sizes, int n_in,
                              void* d_out, int out_size) {
    const float* anchor = (const float*)d_in[0];
    const float* pos    = (const float*)d_in[1];
    const float* lb     = (const float*)d_in[2];
    const float* oh     = (const float*)d_in[3];
    const float* lgx    = (const float*)d_in[4];
    float* out = (float*)d_out;

    const size_t nA  = (size_t)NU * DD;
    const size_t nP  = (size_t)NU * DD;
    const size_t nL  = (size_t)2 * NL * DD;
    const size_t nOH = (size_t)2 * NL * CC;
    const size_t nLG = (size_t)2 * NL * CC;
    size_t oA  = 0;
    size_t oP  = oA + nA;
    size_t oL  = oP + nP;
    size_t oOH = oL + nL;
    size_t oLG = oOH + nOH;
    size_t oU1 = oLG + nLG;

    // fused copy+normalize for anchor/positive; plain copies for lb/lgx
    copy_norm_q_k<<<NU / 8, 256>>>(anchor, out + oA, 0);
    copy_norm_q_k<<<NU / 8, 256>>>(pos,    out + oP, 1);
    copy_f4<<<(int)(nL  / 4 + 255) / 256, 256>>>((const float4*)lb,  (float4*)(out + oL),  (int)(nL  / 4));
    copy_labels_k<<<(2 * NL) / 8, 256>>>(oh, out + oOH);
    copy_f4<<<(int)(nLG / 4 + 255) / 256, 256>>>((const float4*)lgx, (float4*)(out + oLG), (int)(nLG / 4));

    // counting sort (parallel scan for offsets)
    zero_counts_k<<<(2 * CC + 255) / 256, 256>>>();
    count_k<<<(2 * NL + 255) / 256, 256>>>();
    offsets_scan_k<<<2, 1024>>>();
    scatter_k<<<(2 * NL + 255) / 256, 256>>>();

    // supports: normalize in class-sorted order
    norm_sup_k<<<(2 * NL) / 8, 256>>>(lb);

    // zero accumulation targets
    zero_acc_k<<<(int)(((size_t)2 * NU * CC + 255) / 256), 256>>>(out + oU1);

    // GEMM with fused exp + class partial-sum epilogue
    cudaFuncSetAttribute(gemm_fused_k, cudaFuncAttributeMaxDynamicSharedMemorySize, GEMM_SMEM);
    dim3 gg(NL / BN, NU / BM, 2);
    gemm_fused_k<<<gg, 256, GEMM_SMEM>>>(out + oU1);

    // normalize + zero empty classes
    dim3 gn(NU, 2);
    normalize_k<<<gn, 256>>>(out + oU1);
}